// round 15
// baseline (speedup 1.0000x reference)
#include <cuda_runtime.h>
#include <cuda_bf16.h>
#include <cstdint>

#define NROWS 262144
#define DD 128
#define HH 16
#define EE 21

#define THREADS 512                // 16 warps, each autonomous
#define M_TILE 128                 // rows per tile (16 warps x 8 rows)
#define GRID_MAIN 148
#define NBLK 128                   // hist/scatter blocks (2048 rows each)

#define WROW_BYTES 528             // 512 + 16 pad: bank(word w, row r) = (4r + w) % 32
#define WSLOT_BYTES (8 * WROW_BYTES)          // 4224 per warp-slot
#define XS_BYTES (16 * 3 * WSLOT_BYTES)       // 202752
#define SMEM_BYTES (XS_BYTES + 16 * 3 * 8 + 64)

__device__ int g_blockHist[NBLK * EE];
__device__ int g_blockBase[NBLK * EE];
__device__ int g_offsets[EE + 1];
__device__ int g_numTiles;
__device__ int g_tileMap[EE * 128];       // (e<<16)|ti, expert-major order
__device__ int g_perm[NROWS];
__device__ float g_Wsplit[EE][DD * HH];   // tf32-rounded W1, [d][h] contiguous
__device__ unsigned int g_arrive;         // last-block-arrival counter (reset each run)

// ---------------- K1: fused histogram + scan + tile map + W prep ----------------
__global__ void k_hist_scan(const int* __restrict__ sid, const float* __restrict__ W1) {
    __shared__ int sh[EE];
    int tid = threadIdx.x;
    if (tid < EE) sh[tid] = 0;
    __syncthreads();
    {   // 2048 rows per block, int4 vectorized
        int4 v = ((const int4*)sid)[blockIdx.x * blockDim.x + tid];
        atomicAdd(&sh[v.x], 1);
        atomicAdd(&sh[v.y], 1);
        atomicAdd(&sh[v.z], 1);
        atomicAdd(&sh[v.w], 1);
    }
    __syncthreads();
    if (tid < EE) g_blockHist[blockIdx.x * EE + tid] = sh[tid];

    // last-arriving block finalizes
    __shared__ int sIsLast;
    __threadfence();
    __syncthreads();
    if (tid == 0) {
        unsigned int prev = atomicAdd(&g_arrive, 1u);
        sIsLast = (prev == NBLK - 1) ? 1 : 0;
    }
    __syncthreads();
    if (!sIsLast) return;

    __shared__ int hb[NBLK * EE];
    __shared__ int s_cnt[EE], s_tiles[EE], s_off[EE + 1], s_tbase[EE];
    for (int i = tid; i < NBLK * EE; i += blockDim.x) hb[i] = g_blockHist[i];
    __syncthreads();
    if (tid < EE) {
        int c = 0;
        for (int b = 0; b < NBLK; b++) c += hb[b * EE + tid];
        s_cnt[tid] = c;
        s_tiles[tid] = (c + M_TILE - 1) / M_TILE;
    }
    __syncthreads();
    if (tid == 0) {
        int o = 0, T = 0;
        for (int e = 0; e < EE; e++) {
            s_off[e] = o;
            s_tbase[e] = T;
            o += s_cnt[e];
            T += s_tiles[e];
        }
        s_off[EE] = o;
        g_numTiles = T;
        g_arrive = 0;                      // reset for next graph replay
    }
    __syncthreads();
    if (tid <= EE) g_offsets[tid] = s_off[tid];
    if (tid < EE) {
        int run = s_off[tid];
        for (int b = 0; b < NBLK; b++) {
            g_blockBase[b * EE + tid] = run;
            run += hb[b * EE + tid];
        }
    }
    // expert-major tile map
    for (int p = tid; p < EE * 128; p += blockDim.x) {
        int e = p >> 7, ti = p & 127;
        if (ti < s_tiles[e]) g_tileMap[s_tbase[e] + ti] = (e << 16) | ti;
    }
    // tf32 weight prep (21 x 2048 floats)
    for (int i = tid; i < EE * DD * HH; i += blockDim.x) {
        float w = W1[i];
        uint32_t hbv;
        asm("cvt.rna.tf32.f32 %0, %1;" : "=r"(hbv) : "f"(w));
        ((float*)g_Wsplit)[i] = __uint_as_float(hbv);
    }
}

// ---------------- K2: deterministic scatter ----------------
__global__ void k_scatter(const int* __restrict__ sid) {
    __shared__ int sh[EE];
    __shared__ int base[EE];
    int tid = threadIdx.x;
    if (tid < EE) {
        sh[tid] = 0;
        base[tid] = g_blockBase[blockIdx.x * EE + tid];
    }
    __syncthreads();
    int idx = blockIdx.x * blockDim.x + tid;
    int4 v = ((const int4*)sid)[idx];
    int gid = idx * 4;
    int r0 = atomicAdd(&sh[v.x], 1);
    int r1 = atomicAdd(&sh[v.y], 1);
    int r2 = atomicAdd(&sh[v.z], 1);
    int r3 = atomicAdd(&sh[v.w], 1);
    g_perm[base[v.x] + r0] = gid;
    g_perm[base[v.y] + r1] = gid + 1;
    g_perm[base[v.z] + r2] = gid + 2;
    g_perm[base[v.w] + r3] = gid + 3;
}

// ---------------- K3: warp-autonomous bulk-copy + tf32-MMA ----------------
#define MMA_TF32(C0,C1,C2,C3, A0,A1,A2,A3, B0,B1)                                  \
    asm volatile("mma.sync.aligned.m16n8k8.row.col.f32.tf32.tf32.f32 "             \
        "{%0,%1,%2,%3}, {%4,%5,%6,%7}, {%8,%9}, {%0,%1,%2,%3};"                    \
        : "+f"(C0), "+f"(C1), "+f"(C2), "+f"(C3)                                   \
        : "r"(A0), "r"(A1), "r"(A2), "r"(A3), "r"(B0), "r"(B1))

__device__ __forceinline__ void mbar_init(uint32_t mbar, uint32_t count) {
    asm volatile("mbarrier.init.shared.b64 [%0], %1;" :: "r"(mbar), "r"(count) : "memory");
}
__device__ __forceinline__ void mbar_expect_tx(uint32_t mbar, uint32_t bytes) {
    asm volatile("mbarrier.arrive.expect_tx.shared.b64 _, [%0], %1;"
                 :: "r"(mbar), "r"(bytes) : "memory");
}
__device__ __forceinline__ void mbar_wait(uint32_t mbar, uint32_t parity) {
    uint32_t done;
    asm volatile(
        "{\n\t.reg .pred p;\n\t"
        "mbarrier.try_wait.parity.acquire.cta.shared::cta.b64 p, [%1], %2;\n\t"
        "selp.b32 %0, 1, 0, p;\n\t}"
        : "=r"(done) : "r"(mbar), "r"(parity) : "memory");
    if (!done) {
        asm volatile(
            "{\n\t.reg .pred P1;\n\t"
            "WAIT_LOOP_%=:\n\t"
            "mbarrier.try_wait.parity.acquire.cta.shared::cta.b64 P1, [%0], %1, 0x989680;\n\t"
            "@P1 bra.uni WAIT_DONE_%=;\n\t"
            "bra.uni WAIT_LOOP_%=;\n\t"
            "WAIT_DONE_%=:\n\t}"
            :: "r"(mbar), "r"(parity) : "memory");
    }
}
__device__ __forceinline__ void bulk_cp512(uint32_t dst, const void* src, uint32_t mbar) {
    asm volatile(
        "cp.async.bulk.shared::cta.global.mbarrier::complete_tx::bytes [%0], [%1], 512, [%2];"
        :: "r"(dst), "l"(src), "r"(mbar) : "memory");
}

__global__ __launch_bounds__(THREADS, 1)
void k_main(const float* __restrict__ x,
            const float* __restrict__ W1,
            const float* __restrict__ b1,
            const float* __restrict__ W2,
            const float* __restrict__ b2,
            float* __restrict__ out)
{
    extern __shared__ float smem[];
    uint32_t xs_sh = (uint32_t)__cvta_generic_to_shared(smem);
    uint32_t mb_sh = (xs_sh + XS_BYTES + 15u) & ~15u;

    int nT = g_numTiles;
    int b = blockIdx.x;
    int q = (nT + GRID_MAIN - 1) / GRID_MAIN;
    int t0 = b * q;
    int t1 = t0 + q; if (t1 > nT) t1 = nT;
    int n = t1 - t0;
    if (n <= 0) return;

    int tid = threadIdx.x;
    int wid = tid >> 5;
    int t = tid & 31;

    if (tid < 48) mbar_init(mb_sh + (uint32_t)tid * 8u, 1);
    asm volatile("fence.proxy.async.shared::cta;" ::: "memory");
    __syncthreads();

    auto tile_meta = [&](int i, int& e, int& rs, int& v) {
        int m = g_tileMap[t0 + i];
        e = m >> 16;
        int ti = m & 0xFFFF;
        rs = g_offsets[e] + ti * M_TILE;
        v = g_offsets[e + 1] - rs;
        if (v > M_TILE) v = M_TILE;
    };

    // stage slab i into this warp's slot i%3; returns this lane's row (lanes 0-7)
    auto stage = [&](int i) -> int {
        int e, rs, v;
        tile_meta(i, e, rs, v);
        int row = 0;
        if (t < 8) {
            int idx = wid * 8 + t;
            row = g_perm[rs + ((idx < v) ? idx : 0)];
        }
        uint32_t slotb = xs_sh + (uint32_t)((wid * 3 + (i % 3)) * WSLOT_BYTES);
        uint32_t mbar  = mb_sh + (uint32_t)((wid * 3 + (i % 3)) * 8);
        asm volatile("fence.proxy.async.shared::cta;" ::: "memory");
        if (t == 0) mbar_expect_tx(mbar, 4096u);
        if (t < 8) bulk_cp512(slotb + (uint32_t)t * WROW_BYTES, x + (size_t)row * DD, mbar);
        return row;
    };

    int rowS0 = stage(0);
    int rowS1 = (n > 1) ? stage(1) : 0;

    uint32_t aw0[16], aw1[16], aw2[16], aw3[16];
    float b1lo = 0.f, b1hi = 0.f, w2lo = 0.f, w2hi = 0.f, b2v = 0.f;
    int eReg = -1;
    int h = t >> 2;
    uint32_t lane_off = (uint32_t)((t >> 2) * WROW_BYTES + (t & 3) * 4);

    for (int j = 0; j < n; j++) {
        int slot = j % 3;
        uint32_t parity = (uint32_t)((j / 3) & 1);

        int rowS2 = (j + 2 < n) ? stage(j + 2) : 0;

        int ej, rsj, vj;
        tile_meta(j, ej, rsj, vj);

        // reload W frags + scalars on expert change (rare: expert-major chunks)
        if (ej != eReg) {
            eReg = ej;
            const float* Ws = g_Wsplit[ej];
            #pragma unroll
            for (int k = 0; k < 16; k++) {
                int base = (8 * k + (t & 3)) * HH + h;
                aw0[k] = __float_as_uint(Ws[base]);         // [d][h]
                aw1[k] = __float_as_uint(Ws[base + 8]);     // h+8
                aw2[k] = __float_as_uint(Ws[base + 64]);    // d+4
                aw3[k] = __float_as_uint(Ws[base + 72]);    // h+8, d+4
            }
            b1lo = __ldg(b1 + ej * HH + h);
            b1hi = __ldg(b1 + ej * HH + h + 8);
            w2lo = __ldg(W2 + ej * HH + h);
            w2hi = __ldg(W2 + ej * HH + h + 8);
            b2v  = __ldg(b2 + ej);
        }

        mbar_wait(mb_sh + (uint32_t)((wid * 3 + slot) * 8), parity);

        // ---- compute: warp's 8 rows x 128 d -> 16 h, hi+lo chains ----
        uint32_t xb = xs_sh + (uint32_t)((wid * 3 + slot) * WSLOT_BYTES) + lane_off;
        float ch0 = 0.f, ch1 = 0.f, ch2 = 0.f, ch3 = 0.f;
        float cl0 = 0.f, cl1 = 0.f, cl2 = 0.f, cl3 = 0.f;

        #pragma unroll
        for (int k = 0; k < 16; k++) {
            uint32_t a00 = xb + (uint32_t)(k * 32);   // d = 8k + t%4
            float f00, f01;
            asm("ld.shared.f32 %0, [%1];" : "=f"(f00) : "r"(a00));
            asm("ld.shared.f32 %0, [%1];" : "=f"(f01) : "r"(a00 + 16));  // d+4
            uint32_t h00, h01;
            asm("cvt.rna.tf32.f32 %0, %1;" : "=r"(h00) : "f"(f00));
            asm("cvt.rna.tf32.f32 %0, %1;" : "=r"(h01) : "f"(f01));
            uint32_t l00 = __float_as_uint(f00 - __uint_as_float(h00));
            uint32_t l01 = __float_as_uint(f01 - __uint_as_float(h01));
            MMA_TF32(ch0, ch1, ch2, ch3, aw0[k], aw1[k], aw2[k], aw3[k], h00, h01);
            MMA_TF32(cl0, cl1, cl2, cl3, aw0[k], aw1[k], aw2[k], aw3[k], l00, l01);
        }

        // ---- epilogue: relu, dot w2, h-reduce via shfl, store ----
        {
            float pe = fmaxf(ch0 + cl0 + b1lo, 0.f) * w2lo
                     + fmaxf(ch2 + cl2 + b1hi, 0.f) * w2hi;
            float po = fmaxf(ch1 + cl1 + b1lo, 0.f) * w2lo
                     + fmaxf(ch3 + cl3 + b1hi, 0.f) * w2hi;
            #pragma unroll
            for (int d = 4; d < 32; d <<= 1) {
                pe += __shfl_xor_sync(0xFFFFFFFFu, pe, d);
                po += __shfl_xor_sync(0xFFFFFFFFu, po, d);
            }
            int row_e = __shfl_sync(0xFFFFFFFFu, rowS0, 2 * t);
            int row_o = __shfl_sync(0xFFFFFFFFu, rowS0, 2 * t + 1);
            if (t < 4) {
                int r0 = wid * 8 + 2 * t;
                if (r0 < vj)     out[row_e] = fmaxf(pe + b2v, 0.f);
                if (r0 + 1 < vj) out[row_o] = fmaxf(po + b2v, 0.f);
            }
        }

        rowS0 = rowS1;
        rowS1 = rowS2;
    }
}

extern "C" void kernel_launch(void* const* d_in, const int* in_sizes, int n_in,
                              void* d_out, int out_size)
{
    const float* x   = (const float*)d_in[0];
    const int*   sid = (const int*)d_in[1];
    const float* W1  = (const float*)d_in[2];
    const float* b1  = (const float*)d_in[3];
    const float* W2  = (const float*)d_in[4];
    const float* b2  = (const float*)d_in[5];
    float* out = (float*)d_out;

    static bool attr_set = false;
    if (!attr_set) {
        cudaFuncSetAttribute(k_main, cudaFuncAttributeMaxDynamicSharedMemorySize, SMEM_BYTES);
        attr_set = true;
    }

    k_hist_scan<<<NBLK, 512>>>(sid, W1);
    k_scatter<<<NBLK, 512>>>(sid);
    k_main<<<GRID_MAIN, THREADS, SMEM_BYTES>>>(x, W1, b1, W2, b2, out);
}

// round 16
// speedup vs baseline: 1.1399x; 1.1399x over previous
#include <cuda_runtime.h>
#include <cuda_bf16.h>
#include <cstdint>

#define NROWS 262144
#define DD 128
#define HH 16
#define EE 21

#define THREADS 384                // 12 warps, each autonomous
#define NWARP 12
#define RING 4
#define M_TILE 96                  // rows per tile (12 warps x 8 rows)
#define GRID_MAIN 148
#define NBLK 64
#define MAXTPE 256                 // max tiles per expert in map

#define WROW_BYTES 528             // 512 + 16 pad: bank(word w, row r) = (4r + w) % 32
#define WSLOT_BYTES (8 * WROW_BYTES)              // 4224 per warp-slot
#define XS_BYTES (NWARP * RING * WSLOT_BYTES)     // 202752
#define SMEM_BYTES (XS_BYTES + NWARP * RING * 8 + 64)

__device__ int g_blockHist[NBLK * EE];
__device__ int g_blockBase[NBLK * EE];
__device__ int g_offsets[EE + 1];
__device__ int g_numTiles;
__device__ int g_tileMap[EE * MAXTPE];    // (e<<16)|ti, expert-major order
__device__ int g_perm[NROWS];
__device__ float g_Wsplit[EE][DD * HH];   // tf32-rounded W1, [d][h] contiguous

// ---------------- K1: per-block histogram ----------------
__global__ void k_hist(const int* __restrict__ sid) {
    __shared__ int sh[EE];
    int tid = threadIdx.x;
    if (tid < EE) sh[tid] = 0;
    __syncthreads();
    int4 v = ((const int4*)sid)[blockIdx.x * blockDim.x + tid];
    atomicAdd(&sh[v.x], 1);
    atomicAdd(&sh[v.y], 1);
    atomicAdd(&sh[v.z], 1);
    atomicAdd(&sh[v.w], 1);
    __syncthreads();
    if (tid < EE) g_blockHist[blockIdx.x * EE + tid] = sh[tid];
}

// ---------------- K2: block0 = scan + bases + e-major tile map; 1..21 = W prep ----
__global__ void k_scan_prep(const float* __restrict__ W1) {
    if (blockIdx.x == 0) {
        __shared__ int hb[NBLK * EE];
        __shared__ int s_cnt[EE], s_tiles[EE], s_off[EE + 1], s_tbase[EE];
        int tid = threadIdx.x;
        for (int i = tid; i < NBLK * EE; i += blockDim.x) hb[i] = g_blockHist[i];
        __syncthreads();
        if (tid < EE) {
            int c = 0;
            for (int b = 0; b < NBLK; b++) c += hb[b * EE + tid];
            s_cnt[tid] = c;
            s_tiles[tid] = (c + M_TILE - 1) / M_TILE;
        }
        __syncthreads();
        if (tid == 0) {
            int o = 0, T = 0;
            for (int e = 0; e < EE; e++) {
                s_off[e] = o;
                s_tbase[e] = T;
                o += s_cnt[e];
                T += s_tiles[e];
            }
            s_off[EE] = o;
            g_numTiles = T;
        }
        __syncthreads();
        if (tid <= EE) g_offsets[tid] = s_off[tid];
        if (tid < EE) {
            int run = s_off[tid];
            for (int b = 0; b < NBLK; b++) {
                g_blockBase[b * EE + tid] = run;
                run += hb[b * EE + tid];
            }
        }
        for (int p = tid; p < EE * MAXTPE; p += blockDim.x) {
            int e = p / MAXTPE, ti = p % MAXTPE;
            if (ti < s_tiles[e]) g_tileMap[s_tbase[e] + ti] = (e << 16) | ti;
        }
    } else {
        int e = blockIdx.x - 1;
        for (int i = threadIdx.x; i < DD * HH; i += blockDim.x) {
            float w = W1[e * DD * HH + i];
            uint32_t hbv;
            asm("cvt.rna.tf32.f32 %0, %1;" : "=r"(hbv) : "f"(w));
            g_Wsplit[e][i] = __uint_as_float(hbv);
        }
    }
}

// ---------------- K3: deterministic scatter ----------------
__global__ void k_scatter(const int* __restrict__ sid) {
    __shared__ int sh[EE];
    __shared__ int base[EE];
    int tid = threadIdx.x;
    if (tid < EE) {
        sh[tid] = 0;
        base[tid] = g_blockBase[blockIdx.x * EE + tid];
    }
    __syncthreads();
    int idx = blockIdx.x * blockDim.x + tid;
    int4 v = ((const int4*)sid)[idx];
    int gid = idx * 4;
    int r0 = atomicAdd(&sh[v.x], 1);
    int r1 = atomicAdd(&sh[v.y], 1);
    int r2 = atomicAdd(&sh[v.z], 1);
    int r3 = atomicAdd(&sh[v.w], 1);
    g_perm[base[v.x] + r0] = gid;
    g_perm[base[v.y] + r1] = gid + 1;
    g_perm[base[v.z] + r2] = gid + 2;
    g_perm[base[v.w] + r3] = gid + 3;
}

// ---------------- K4: warp-autonomous ring-4 bulk-copy + tf32-MMA ----------
#define MMA_TF32(C0,C1,C2,C3, A0,A1,A2,A3, B0,B1)                                  \
    asm volatile("mma.sync.aligned.m16n8k8.row.col.f32.tf32.tf32.f32 "             \
        "{%0,%1,%2,%3}, {%4,%5,%6,%7}, {%8,%9}, {%0,%1,%2,%3};"                    \
        : "+f"(C0), "+f"(C1), "+f"(C2), "+f"(C3)                                   \
        : "r"(A0), "r"(A1), "r"(A2), "r"(A3), "r"(B0), "r"(B1))

__device__ __forceinline__ void mbar_init(uint32_t mbar, uint32_t count) {
    asm volatile("mbarrier.init.shared.b64 [%0], %1;" :: "r"(mbar), "r"(count) : "memory");
}
__device__ __forceinline__ void mbar_expect_tx(uint32_t mbar, uint32_t bytes) {
    asm volatile("mbarrier.arrive.expect_tx.shared.b64 _, [%0], %1;"
                 :: "r"(mbar), "r"(bytes) : "memory");
}
__device__ __forceinline__ void mbar_wait(uint32_t mbar, uint32_t parity) {
    uint32_t done;
    asm volatile(
        "{\n\t.reg .pred p;\n\t"
        "mbarrier.try_wait.parity.acquire.cta.shared::cta.b64 p, [%1], %2;\n\t"
        "selp.b32 %0, 1, 0, p;\n\t}"
        : "=r"(done) : "r"(mbar), "r"(parity) : "memory");
    if (!done) {
        asm volatile(
            "{\n\t.reg .pred P1;\n\t"
            "WAIT_LOOP_%=:\n\t"
            "mbarrier.try_wait.parity.acquire.cta.shared::cta.b64 P1, [%0], %1, 0x989680;\n\t"
            "@P1 bra.uni WAIT_DONE_%=;\n\t"
            "bra.uni WAIT_LOOP_%=;\n\t"
            "WAIT_DONE_%=:\n\t}"
            :: "r"(mbar), "r"(parity) : "memory");
    }
}
__device__ __forceinline__ void bulk_cp512(uint32_t dst, const void* src, uint32_t mbar) {
    asm volatile(
        "cp.async.bulk.shared::cta.global.mbarrier::complete_tx::bytes [%0], [%1], 512, [%2];"
        :: "r"(dst), "l"(src), "r"(mbar) : "memory");
}

__global__ __launch_bounds__(THREADS, 1)
void k_main(const float* __restrict__ x,
            const float* __restrict__ W1,
            const float* __restrict__ b1,
            const float* __restrict__ W2,
            const float* __restrict__ b2,
            float* __restrict__ out)
{
    extern __shared__ float smem[];
    uint32_t xs_sh = (uint32_t)__cvta_generic_to_shared(smem);
    uint32_t mb_sh = (xs_sh + XS_BYTES + 15u) & ~15u;

    int nT = g_numTiles;
    int b = blockIdx.x;
    int q = (nT + GRID_MAIN - 1) / GRID_MAIN;
    int t0 = b * q;
    int t1 = t0 + q; if (t1 > nT) t1 = nT;
    int n = t1 - t0;
    if (n <= 0) return;

    int tid = threadIdx.x;
    int wid = tid >> 5;
    int t = tid & 31;

    if (tid < NWARP * RING) mbar_init(mb_sh + (uint32_t)tid * 8u, 1);
    asm volatile("fence.proxy.async.shared::cta;" ::: "memory");
    __syncthreads();

    auto tile_meta = [&](int i, int& e, int& rs, int& v) {
        int m = g_tileMap[t0 + i];
        e = m >> 16;
        int ti = m & 0xFFFF;
        rs = g_offsets[e] + ti * M_TILE;
        v = g_offsets[e + 1] - rs;
        if (v > M_TILE) v = M_TILE;
    };

    // stage slab i into this warp's slot i%RING; returns this lane's row (lanes 0-7)
    auto stage = [&](int i) -> int {
        int e, rs, v;
        tile_meta(i, e, rs, v);
        int row = 0;
        if (t < 8) {
            int idx = wid * 8 + t;
            row = g_perm[rs + ((idx < v) ? idx : 0)];
        }
        uint32_t slotb = xs_sh + (uint32_t)((wid * RING + (i % RING)) * WSLOT_BYTES);
        uint32_t mbar  = mb_sh + (uint32_t)((wid * RING + (i % RING)) * 8);
        asm volatile("fence.proxy.async.shared::cta;" ::: "memory");
        if (t == 0) mbar_expect_tx(mbar, 4096u);
        if (t < 8) bulk_cp512(slotb + (uint32_t)t * WROW_BYTES, x + (size_t)row * DD, mbar);
        return row;
    };

    // prologue: stage slabs 0..2 (lookahead 3)
    int rowS0 = stage(0);
    int rowS1 = (n > 1) ? stage(1) : 0;
    int rowS2 = (n > 2) ? stage(2) : 0;

    uint32_t aw0[16], aw1[16], aw2[16], aw3[16];
    float b1lo = 0.f, b1hi = 0.f, w2lo = 0.f, w2hi = 0.f, b2v = 0.f;
    int eReg = -1;
    int h = t >> 2;
    uint32_t lane_off = (uint32_t)((t >> 2) * WROW_BYTES + (t & 3) * 4);

    for (int j = 0; j < n; j++) {
        int slot = j % RING;
        uint32_t parity = (uint32_t)((j / RING) & 1);

        int rowS3 = (j + 3 < n) ? stage(j + 3) : 0;

        int ej, rsj, vj;
        tile_meta(j, ej, rsj, vj);

        // reload W frags + scalars on expert change (rare: expert-major chunks)
        if (ej != eReg) {
            eReg = ej;
            const float* Ws = g_Wsplit[ej];
            #pragma unroll
            for (int k = 0; k < 16; k++) {
                int base = (8 * k + (t & 3)) * HH + h;
                aw0[k] = __float_as_uint(Ws[base]);         // [d][h]
                aw1[k] = __float_as_uint(Ws[base + 8]);     // h+8
                aw2[k] = __float_as_uint(Ws[base + 64]);    // d+4
                aw3[k] = __float_as_uint(Ws[base + 72]);    // h+8, d+4
            }
            b1lo = __ldg(b1 + ej * HH + h);
            b1hi = __ldg(b1 + ej * HH + h + 8);
            w2lo = __ldg(W2 + ej * HH + h);
            w2hi = __ldg(W2 + ej * HH + h + 8);
            b2v  = __ldg(b2 + ej);
        }

        mbar_wait(mb_sh + (uint32_t)((wid * RING + slot) * 8), parity);

        // ---- compute: warp's 8 rows x 128 d -> 16 h, hi+lo chains ----
        uint32_t xb = xs_sh + (uint32_t)((wid * RING + slot) * WSLOT_BYTES) + lane_off;
        float ch0 = 0.f, ch1 = 0.f, ch2 = 0.f, ch3 = 0.f;
        float cl0 = 0.f, cl1 = 0.f, cl2 = 0.f, cl3 = 0.f;

        #pragma unroll
        for (int k = 0; k < 16; k++) {
            uint32_t a00 = xb + (uint32_t)(k * 32);   // d = 8k + t%4
            float f00, f01;
            asm("ld.shared.f32 %0, [%1];" : "=f"(f00) : "r"(a00));
            asm("ld.shared.f32 %0, [%1];" : "=f"(f01) : "r"(a00 + 16));  // d+4
            uint32_t h00, h01;
            asm("cvt.rna.tf32.f32 %0, %1;" : "=r"(h00) : "f"(f00));
            asm("cvt.rna.tf32.f32 %0, %1;" : "=r"(h01) : "f"(f01));
            uint32_t l00 = __float_as_uint(f00 - __uint_as_float(h00));
            uint32_t l01 = __float_as_uint(f01 - __uint_as_float(h01));
            MMA_TF32(ch0, ch1, ch2, ch3, aw0[k], aw1[k], aw2[k], aw3[k], h00, h01);
            MMA_TF32(cl0, cl1, cl2, cl3, aw0[k], aw1[k], aw2[k], aw3[k], l00, l01);
        }

        // ---- epilogue: relu, dot w2, h-reduce via shfl, store ----
        {
            float pe = fmaxf(ch0 + cl0 + b1lo, 0.f) * w2lo
                     + fmaxf(ch2 + cl2 + b1hi, 0.f) * w2hi;
            float po = fmaxf(ch1 + cl1 + b1lo, 0.f) * w2lo
                     + fmaxf(ch3 + cl3 + b1hi, 0.f) * w2hi;
            #pragma unroll
            for (int d = 4; d < 32; d <<= 1) {
                pe += __shfl_xor_sync(0xFFFFFFFFu, pe, d);
                po += __shfl_xor_sync(0xFFFFFFFFu, po, d);
            }
            int row_e = __shfl_sync(0xFFFFFFFFu, rowS0, 2 * t);
            int row_o = __shfl_sync(0xFFFFFFFFu, rowS0, 2 * t + 1);
            if (t < 4) {
                int r0 = wid * 8 + 2 * t;
                if (r0 < vj)     out[row_e] = fmaxf(pe + b2v, 0.f);
                if (r0 + 1 < vj) out[row_o] = fmaxf(po + b2v, 0.f);
            }
        }

        rowS0 = rowS1;
        rowS1 = rowS2;
        rowS2 = rowS3;
    }
}

extern "C" void kernel_launch(void* const* d_in, const int* in_sizes, int n_in,
                              void* d_out, int out_size)
{
    const float* x   = (const float*)d_in[0];
    const int*   sid = (const int*)d_in[1];
    const float* W1  = (const float*)d_in[2];
    const float* b1  = (const float*)d_in[3];
    const float* W2  = (const float*)d_in[4];
    const float* b2  = (const float*)d_in[5];
    float* out = (float*)d_out;

    static bool attr_set = false;
    if (!attr_set) {
        cudaFuncSetAttribute(k_main, cudaFuncAttributeMaxDynamicSharedMemorySize, SMEM_BYTES);
        attr_set = true;
    }

    k_hist<<<NBLK, 1024>>>(sid);
    k_scan_prep<<<1 + EE, 1024>>>(W1);
    k_scatter<<<NBLK, 1024>>>(sid);
    k_main<<<GRID_MAIN, THREADS, SMEM_BYTES>>>(x, W1, b1, W2, b2, out);
}

// round 17
// speedup vs baseline: 1.2586x; 1.1042x over previous
#include <cuda_runtime.h>
#include <cuda_bf16.h>
#include <cstdint>

#define NROWS 262144
#define DD 128
#define HH 16
#define EE 21

#define THREADS 512                // 16 warps, each autonomous
#define M_TILE 128                 // rows per tile (16 warps x 8 rows)
#define GRID_MAIN 148
#define NBLK 64                    // hist/scatter blocks (4096 rows each)

#define WROW_BYTES 528             // 512 + 16 pad: bank(word w, row r) = (4r + w) % 32
#define WSLOT_BYTES (8 * WROW_BYTES)          // 4224 per warp-slot
#define XS_BYTES (16 * 3 * WSLOT_BYTES)       // 202752
#define SMEM_BYTES (XS_BYTES + 16 * 3 * 8 + 64)

__device__ int g_blockHist[NBLK * EE];
__device__ int g_blockBase[NBLK * EE];
__device__ int g_offsets[EE + 1];
__device__ int g_numTiles;
__device__ int g_tileMap[EE * 128];       // (e<<16)|ti, expert-major order
__device__ int g_perm[NROWS];
__device__ float g_Wsplit[EE][DD * HH];   // tf32-rounded W1, [d][h] contiguous

// ---------------- K1: per-block histogram (int4, 4096 rows/block) ----------------
__global__ void k_hist(const int* __restrict__ sid) {
    __shared__ int sh[EE];
    int tid = threadIdx.x;
    if (tid < EE) sh[tid] = 0;
    __syncthreads();
    int4 v = ((const int4*)sid)[blockIdx.x * blockDim.x + tid];
    atomicAdd(&sh[v.x], 1);
    atomicAdd(&sh[v.y], 1);
    atomicAdd(&sh[v.z], 1);
    atomicAdd(&sh[v.w], 1);
    __syncthreads();
    if (tid < EE) g_blockHist[blockIdx.x * EE + tid] = sh[tid];
}

// ---------------- K2: block0 = scan + bases + e-major tile map; 1..21 = W prep ----
__global__ void k_scan_prep(const float* __restrict__ W1) {
    if (blockIdx.x == 0) {
        __shared__ int hb[NBLK * EE];
        __shared__ int s_cnt[EE], s_tiles[EE], s_off[EE + 1], s_tbase[EE];
        int tid = threadIdx.x;
        for (int i = tid; i < NBLK * EE; i += blockDim.x) hb[i] = g_blockHist[i];
        __syncthreads();
        if (tid < EE) {
            int c = 0;
            for (int b = 0; b < NBLK; b++) c += hb[b * EE + tid];
            s_cnt[tid] = c;
            s_tiles[tid] = (c + M_TILE - 1) / M_TILE;
        }
        __syncthreads();
        if (tid == 0) {
            int o = 0, T = 0;
            for (int e = 0; e < EE; e++) {
                s_off[e] = o;
                s_tbase[e] = T;
                o += s_cnt[e];
                T += s_tiles[e];
            }
            s_off[EE] = o;
            g_numTiles = T;
        }
        __syncthreads();
        if (tid <= EE) g_offsets[tid] = s_off[tid];
        if (tid < EE) {
            int run = s_off[tid];
            for (int b = 0; b < NBLK; b++) {
                g_blockBase[b * EE + tid] = run;
                run += hb[b * EE + tid];
            }
        }
        for (int p = tid; p < EE * 128; p += blockDim.x) {
            int e = p >> 7, ti = p & 127;
            if (ti < s_tiles[e]) g_tileMap[s_tbase[e] + ti] = (e << 16) | ti;
        }
    } else {
        int e = blockIdx.x - 1;
        for (int i = threadIdx.x; i < DD * HH; i += blockDim.x) {
            float w = W1[e * DD * HH + i];
            uint32_t hbv;
            asm("cvt.rna.tf32.f32 %0, %1;" : "=r"(hbv) : "f"(w));
            g_Wsplit[e][i] = __uint_as_float(hbv);
        }
    }
}

// ---------------- K3: deterministic scatter (int4, 4096 rows/block) ----------------
__global__ void k_scatter(const int* __restrict__ sid) {
    __shared__ int sh[EE];
    __shared__ int base[EE];
    int tid = threadIdx.x;
    if (tid < EE) {
        sh[tid] = 0;
        base[tid] = g_blockBase[blockIdx.x * EE + tid];
    }
    __syncthreads();
    int idx = blockIdx.x * blockDim.x + tid;
    int4 v = ((const int4*)sid)[idx];
    int gid = idx * 4;
    int r0 = atomicAdd(&sh[v.x], 1);
    int r1 = atomicAdd(&sh[v.y], 1);
    int r2 = atomicAdd(&sh[v.z], 1);
    int r3 = atomicAdd(&sh[v.w], 1);
    g_perm[base[v.x] + r0] = gid;
    g_perm[base[v.y] + r1] = gid + 1;
    g_perm[base[v.z] + r2] = gid + 2;
    g_perm[base[v.w] + r3] = gid + 3;
}

// ---------------- K4: warp-autonomous bulk-copy + tf32-MMA (R13 config) -----
#define MMA_TF32(C0,C1,C2,C3, A0,A1,A2,A3, B0,B1)                                  \
    asm volatile("mma.sync.aligned.m16n8k8.row.col.f32.tf32.tf32.f32 "             \
        "{%0,%1,%2,%3}, {%4,%5,%6,%7}, {%8,%9}, {%0,%1,%2,%3};"                    \
        : "+f"(C0), "+f"(C1), "+f"(C2), "+f"(C3)                                   \
        : "r"(A0), "r"(A1), "r"(A2), "r"(A3), "r"(B0), "r"(B1))

__device__ __forceinline__ void mbar_init(uint32_t mbar, uint32_t count) {
    asm volatile("mbarrier.init.shared.b64 [%0], %1;" :: "r"(mbar), "r"(count) : "memory");
}
__device__ __forceinline__ void mbar_expect_tx(uint32_t mbar, uint32_t bytes) {
    asm volatile("mbarrier.arrive.expect_tx.shared.b64 _, [%0], %1;"
                 :: "r"(mbar), "r"(bytes) : "memory");
}
__device__ __forceinline__ void mbar_wait(uint32_t mbar, uint32_t parity) {
    uint32_t done;
    asm volatile(
        "{\n\t.reg .pred p;\n\t"
        "mbarrier.try_wait.parity.acquire.cta.shared::cta.b64 p, [%1], %2;\n\t"
        "selp.b32 %0, 1, 0, p;\n\t}"
        : "=r"(done) : "r"(mbar), "r"(parity) : "memory");
    if (!done) {
        asm volatile(
            "{\n\t.reg .pred P1;\n\t"
            "WAIT_LOOP_%=:\n\t"
            "mbarrier.try_wait.parity.acquire.cta.shared::cta.b64 P1, [%0], %1, 0x989680;\n\t"
            "@P1 bra.uni WAIT_DONE_%=;\n\t"
            "bra.uni WAIT_LOOP_%=;\n\t"
            "WAIT_DONE_%=:\n\t}"
            :: "r"(mbar), "r"(parity) : "memory");
    }
}
__device__ __forceinline__ void bulk_cp512(uint32_t dst, const void* src, uint32_t mbar) {
    asm volatile(
        "cp.async.bulk.shared::cta.global.mbarrier::complete_tx::bytes [%0], [%1], 512, [%2];"
        :: "r"(dst), "l"(src), "r"(mbar) : "memory");
}

__global__ __launch_bounds__(THREADS, 1)
void k_main(const float* __restrict__ x,
            const float* __restrict__ W1,
            const float* __restrict__ b1,
            const float* __restrict__ W2,
            const float* __restrict__ b2,
            float* __restrict__ out)
{
    extern __shared__ float smem[];
    uint32_t xs_sh = (uint32_t)__cvta_generic_to_shared(smem);
    uint32_t mb_sh = (xs_sh + XS_BYTES + 15u) & ~15u;

    int nT = g_numTiles;
    int b = blockIdx.x;
    int q = (nT + GRID_MAIN - 1) / GRID_MAIN;
    int t0 = b * q;
    int t1 = t0 + q; if (t1 > nT) t1 = nT;
    int n = t1 - t0;
    if (n <= 0) return;

    int tid = threadIdx.x;
    int wid = tid >> 5;
    int t = tid & 31;

    if (tid < 48) mbar_init(mb_sh + (uint32_t)tid * 8u, 1);
    asm volatile("fence.proxy.async.shared::cta;" ::: "memory");
    __syncthreads();

    auto tile_meta = [&](int i, int& e, int& rs, int& v) {
        int m = g_tileMap[t0 + i];
        e = m >> 16;
        int ti = m & 0xFFFF;
        rs = g_offsets[e] + ti * M_TILE;
        v = g_offsets[e + 1] - rs;
        if (v > M_TILE) v = M_TILE;
    };

    // stage slab i into this warp's slot i%3; returns this lane's row (lanes 0-7)
    auto stage = [&](int i) -> int {
        int e, rs, v;
        tile_meta(i, e, rs, v);
        int row = 0;
        if (t < 8) {
            int idx = wid * 8 + t;
            row = g_perm[rs + ((idx < v) ? idx : 0)];
        }
        uint32_t slotb = xs_sh + (uint32_t)((wid * 3 + (i % 3)) * WSLOT_BYTES);
        uint32_t mbar  = mb_sh + (uint32_t)((wid * 3 + (i % 3)) * 8);
        asm volatile("fence.proxy.async.shared::cta;" ::: "memory");
        if (t == 0) mbar_expect_tx(mbar, 4096u);
        if (t < 8) bulk_cp512(slotb + (uint32_t)t * WROW_BYTES, x + (size_t)row * DD, mbar);
        return row;
    };

    int rowS0 = stage(0);
    int rowS1 = (n > 1) ? stage(1) : 0;

    uint32_t aw0[16], aw1[16], aw2[16], aw3[16];
    float b1lo = 0.f, b1hi = 0.f, w2lo = 0.f, w2hi = 0.f, b2v = 0.f;
    int eReg = -1;
    int h = t >> 2;
    uint32_t lane_off = (uint32_t)((t >> 2) * WROW_BYTES + (t & 3) * 4);

    for (int j = 0; j < n; j++) {
        int slot = j % 3;
        uint32_t parity = (uint32_t)((j / 3) & 1);

        int rowS2 = (j + 2 < n) ? stage(j + 2) : 0;

        int ej, rsj, vj;
        tile_meta(j, ej, rsj, vj);

        // reload W frags + scalars on expert change (rare: expert-major chunks)
        if (ej != eReg) {
            eReg = ej;
            const float* Ws = g_Wsplit[ej];
            #pragma unroll
            for (int k = 0; k < 16; k++) {
                int base = (8 * k + (t & 3)) * HH + h;
                aw0[k] = __float_as_uint(Ws[base]);         // [d][h]
                aw1[k] = __float_as_uint(Ws[base + 8]);     // h+8
                aw2[k] = __float_as_uint(Ws[base + 64]);    // d+4
                aw3[k] = __float_as_uint(Ws[base + 72]);    // h+8, d+4
            }
            b1lo = __ldg(b1 + ej * HH + h);
            b1hi = __ldg(b1 + ej * HH + h + 8);
            w2lo = __ldg(W2 + ej * HH + h);
            w2hi = __ldg(W2 + ej * HH + h + 8);
            b2v  = __ldg(b2 + ej);
        }

        mbar_wait(mb_sh + (uint32_t)((wid * 3 + slot) * 8), parity);

        // ---- compute: warp's 8 rows x 128 d -> 16 h, hi+lo chains ----
        uint32_t xb = xs_sh + (uint32_t)((wid * 3 + slot) * WSLOT_BYTES) + lane_off;
        float ch0 = 0.f, ch1 = 0.f, ch2 = 0.f, ch3 = 0.f;
        float cl0 = 0.f, cl1 = 0.f, cl2 = 0.f, cl3 = 0.f;

        #pragma unroll
        for (int k = 0; k < 16; k++) {
            uint32_t a00 = xb + (uint32_t)(k * 32);   // d = 8k + t%4
            float f00, f01;
            asm("ld.shared.f32 %0, [%1];" : "=f"(f00) : "r"(a00));
            asm("ld.shared.f32 %0, [%1];" : "=f"(f01) : "r"(a00 + 16));  // d+4
            uint32_t h00, h01;
            asm("cvt.rna.tf32.f32 %0, %1;" : "=r"(h00) : "f"(f00));
            asm("cvt.rna.tf32.f32 %0, %1;" : "=r"(h01) : "f"(f01));
            uint32_t l00 = __float_as_uint(f00 - __uint_as_float(h00));
            uint32_t l01 = __float_as_uint(f01 - __uint_as_float(h01));
            MMA_TF32(ch0, ch1, ch2, ch3, aw0[k], aw1[k], aw2[k], aw3[k], h00, h01);
            MMA_TF32(cl0, cl1, cl2, cl3, aw0[k], aw1[k], aw2[k], aw3[k], l00, l01);
        }

        // ---- epilogue: relu, dot w2, h-reduce via shfl, store ----
        {
            float pe = fmaxf(ch0 + cl0 + b1lo, 0.f) * w2lo
                     + fmaxf(ch2 + cl2 + b1hi, 0.f) * w2hi;
            float po = fmaxf(ch1 + cl1 + b1lo, 0.f) * w2lo
                     + fmaxf(ch3 + cl3 + b1hi, 0.f) * w2hi;
            #pragma unroll
            for (int d = 4; d < 32; d <<= 1) {
                pe += __shfl_xor_sync(0xFFFFFFFFu, pe, d);
                po += __shfl_xor_sync(0xFFFFFFFFu, po, d);
            }
            int row_e = __shfl_sync(0xFFFFFFFFu, rowS0, 2 * t);
            int row_o = __shfl_sync(0xFFFFFFFFu, rowS0, 2 * t + 1);
            if (t < 4) {
                int r0 = wid * 8 + 2 * t;
                if (r0 < vj)     out[row_e] = fmaxf(pe + b2v, 0.f);
                if (r0 + 1 < vj) out[row_o] = fmaxf(po + b2v, 0.f);
            }
        }

        rowS0 = rowS1;
        rowS1 = rowS2;
    }
}

extern "C" void kernel_launch(void* const* d_in, const int* in_sizes, int n_in,
                              void* d_out, int out_size)
{
    const float* x   = (const float*)d_in[0];
    const int*   sid = (const int*)d_in[1];
    const float* W1  = (const float*)d_in[2];
    const float* b1  = (const float*)d_in[3];
    const float* W2  = (const float*)d_in[4];
    const float* b2  = (const float*)d_in[5];
    float* out = (float*)d_out;

    static bool attr_set = false;
    if (!attr_set) {
        cudaFuncSetAttribute(k_main, cudaFuncAttributeMaxDynamicSharedMemorySize, SMEM_BYTES);
        attr_set = true;
    }

    k_hist<<<NBLK, 1024>>>(sid);
    k_scan_prep<<<1 + EE, 1024>>>(W1);
    k_scatter<<<NBLK, 1024>>>(sid);
    k_main<<<GRID_MAIN, THREADS, SMEM_BYTES>>>(x, W1, b1, W2, b2, out);
}